// round 14
// baseline (speedup 1.0000x reference)
#include <cuda_runtime.h>
#include <cuda_fp16.h>
#include <cstdint>

// NeiAttention, 4-kernel form (round 14).
// K0: x,W -> fp16 once.
// K1: y = x @ W            fp16 MMA, pure cp.async staging, split-d 2-stage pipeline
// K2: logits/softmax/z     streams A once (fp32 cp.async), 4 CTAs/SM  [unchanged from R13]
// K3: out = z @ W^T + b    fp16 MMA, pure cp.async staging, split-k 2-stage pipeline

__device__ __half g_y16[16384 * 192];
__device__ __half g_z16[16384 * 192];
__device__ __half g_w16[128 * 192];
__device__ __half g_x16[16384 * 128];

__device__ __forceinline__ uint32_t smem_u32(const void* p) {
    uint32_t a;
    asm("{ .reg .u64 t; cvta.to.shared.u64 t, %1; cvt.u32.u64 %0, t; }" : "=r"(a) : "l"(p));
    return a;
}
__device__ __forceinline__ uint32_t pack_f16x2(float lo, float hi) {
    uint32_t r;
    asm("cvt.rn.f16x2.f32 %0, %1, %2;" : "=r"(r) : "f"(hi), "f"(lo));
    return r;
}
__device__ __forceinline__ void ldsm4(uint32_t r[4], uint32_t addr) {
    asm volatile("ldmatrix.sync.aligned.m8n8.x4.shared.b16 {%0,%1,%2,%3}, [%4];"
                 : "=r"(r[0]), "=r"(r[1]), "=r"(r[2]), "=r"(r[3]) : "r"(addr));
}
__device__ __forceinline__ void ldsm4t(uint32_t r[4], uint32_t addr) {
    asm volatile("ldmatrix.sync.aligned.m8n8.x4.trans.shared.b16 {%0,%1,%2,%3}, [%4];"
                 : "=r"(r[0]), "=r"(r[1]), "=r"(r[2]), "=r"(r[3]) : "r"(addr));
}
__device__ __forceinline__ void mma_f16(float d[4], const uint32_t a[4],
                                        uint32_t b0, uint32_t b1) {
    asm volatile(
        "mma.sync.aligned.m16n8k16.row.col.f32.f16.f16.f32 "
        "{%0,%1,%2,%3}, {%4,%5,%6,%7}, {%8,%9}, {%0,%1,%2,%3};"
        : "+f"(d[0]), "+f"(d[1]), "+f"(d[2]), "+f"(d[3])
        : "r"(a[0]), "r"(a[1]), "r"(a[2]), "r"(a[3]), "r"(b0), "r"(b1));
}
__device__ __forceinline__ void cpa16(uint32_t dst, const void* src) {
    asm volatile("cp.async.cg.shared.global [%0], [%1], 16;" :: "r"(dst), "l"(src));
}
__device__ __forceinline__ void cp_commit() { asm volatile("cp.async.commit_group;" ::: "memory"); }
template <int N>
__device__ __forceinline__ void cp_wait() { asm volatile("cp.async.wait_group %0;" :: "n"(N) : "memory"); }
__device__ __forceinline__ float shflx(float v, int m) { return __shfl_xor_sync(0xffffffffu, v, m); }

// ============================ K0: x, W -> fp16 ============================
__global__ __launch_bounds__(256, 4)
void k0_cvt(const float* __restrict__ W1_w, const float* __restrict__ x)
{
    int i = blockIdx.x * 256 + threadIdx.x;
    if (i < 12288) {                              // W: 24576 floats = 12288 float2
        float2 v = ((const float2*)W1_w)[i];
        ((uint32_t*)g_w16)[i] = pack_f16x2(v.x, v.y);
    }
    // x: 2,097,152 floats = 524288 float4
    for (int j = i; j < 524288; j += gridDim.x * 256) {
        float4 v = ((const float4*)x)[j];
        uint2 w;
        w.x = pack_f16x2(v.x, v.y);
        w.y = pack_f16x2(v.z, v.w);
        ((uint2*)g_x16)[j] = w;
    }
}

// ============================ K1: y = x @ W ============================
// 256 CTAs x 64 rows, 256 thr (warp grid 2x4, warp tile 32x48).
// Pure cp.async: group0 = x d-cols 0..63 + W d-rows 0..63; group1 = the rest.
#define K1_XH   0         // 64*272 = 17408 B
#define K1_WH   17408     // 128*400 = 51200 B
#define K1_BYTES 68608

__global__ __launch_bounds__(256, 2)
void k1_y(int dummy)
{
    extern __shared__ float sm[];
    const uint32_t sb = smem_u32(sm);
    const int tid = threadIdx.x;
    const int wid = tid >> 5, lid = tid & 31;
    const int g = lid >> 2, t4 = lid & 3;
    const int sel = lid >> 3, lr = lid & 7;
    const int wm = wid >> 2, wn = wid & 3;
    const size_t row0 = (size_t)blockIdx.x * 64;

    // group 0: x d 0..63 (512 chunks) + W d-rows 0..63 (1536 chunks)
    #pragma unroll
    for (int it = 0; it < 2; it++) {
        int idx = tid + it * 256;                 // r*8 + c
        int r = idx >> 3, c = idx & 7;
        cpa16(sb + K1_XH + (uint32_t)(r * 272 + c * 16),
              g_x16 + (row0 + r) * 128 + c * 8);
    }
    #pragma unroll
    for (int it = 0; it < 6; it++) {
        int idx = tid + it * 256;                 // r*24 + c
        int r = idx / 24, c = idx - r * 24;
        cpa16(sb + K1_WH + (uint32_t)(r * 400 + c * 16), g_w16 + r * 192 + c * 8);
    }
    cp_commit();
    // group 1: x d 64..127 + W d-rows 64..127
    #pragma unroll
    for (int it = 0; it < 2; it++) {
        int idx = tid + it * 256;
        int r = idx >> 3, c = idx & 7;
        cpa16(sb + K1_XH + (uint32_t)(r * 272 + 128 + c * 16),
              g_x16 + (row0 + r) * 128 + 64 + c * 8);
    }
    #pragma unroll
    for (int it = 0; it < 6; it++) {
        int idx = tid + it * 256;
        int r = 64 + idx / 24, c = idx % 24;
        cpa16(sb + K1_WH + (uint32_t)(r * 400 + c * 16), g_w16 + r * 192 + c * 8);
    }
    cp_commit();

    uint32_t aA[2];
    #pragma unroll
    for (int i = 0; i < 2; i++)
        aA[i] = sb + K1_XH + (uint32_t)(wm * 32 + i * 16 + (sel & 1) * 8 + lr) * 272u
                + (uint32_t)(sel >> 1) * 16u;
    const int drow = (lid & 7) + ((lid >> 3) & 1) * 8;
    const int kgrp = lid >> 4;
    uint32_t bT[3];
    #pragma unroll
    for (int jp = 0; jp < 3; jp++)
        bT[jp] = sb + K1_WH + (uint32_t)drow * 400u
                 + (uint32_t)(wn * 48 + jp * 16 + kgrp * 8) * 2u;

    float acc[2][6][4];
    #pragma unroll
    for (int i = 0; i < 2; i++)
        #pragma unroll
        for (int j = 0; j < 6; j++)
            #pragma unroll
            for (int q = 0; q < 4; q++) acc[i][j][q] = 0.f;

    cp_wait<1>();
    __syncthreads();
    #pragma unroll
    for (int ks = 0; ks < 4; ks++) {
        uint32_t a0[4], a1[4];
        ldsm4(a0, aA[0] + ks * 32);
        ldsm4(a1, aA[1] + ks * 32);
        #pragma unroll
        for (int jp = 0; jp < 3; jp++) {
            uint32_t bt[4];
            ldsm4t(bt, bT[jp] + ks * 6400);       // +16 d-rows * 400 B
            mma_f16(acc[0][2 * jp],     a0, bt[0], bt[1]);
            mma_f16(acc[0][2 * jp + 1], a0, bt[2], bt[3]);
            mma_f16(acc[1][2 * jp],     a1, bt[0], bt[1]);
            mma_f16(acc[1][2 * jp + 1], a1, bt[2], bt[3]);
        }
    }
    cp_wait<0>();
    __syncthreads();
    #pragma unroll
    for (int ks = 4; ks < 8; ks++) {
        uint32_t a0[4], a1[4];
        ldsm4(a0, aA[0] + ks * 32);
        ldsm4(a1, aA[1] + ks * 32);
        #pragma unroll
        for (int jp = 0; jp < 3; jp++) {
            uint32_t bt[4];
            ldsm4t(bt, bT[jp] + ks * 6400);
            mma_f16(acc[0][2 * jp],     a0, bt[0], bt[1]);
            mma_f16(acc[0][2 * jp + 1], a0, bt[2], bt[3]);
            mma_f16(acc[1][2 * jp],     a1, bt[0], bt[1]);
            mma_f16(acc[1][2 * jp + 1], a1, bt[2], bt[3]);
        }
    }

    #pragma unroll
    for (int i = 0; i < 2; i++) {
        int row = blockIdx.x * 64 + wm * 32 + i * 16 + g;
        #pragma unroll
        for (int j = 0; j < 6; j++) {
            int col = wn * 48 + j * 8 + 2 * t4;
            *(uint32_t*)(g_y16 + (size_t)row * 192 + col) =
                pack_f16x2(acc[i][j][0], acc[i][j][1]);
            *(uint32_t*)(g_y16 + (size_t)(row + 8) * 192 + col) =
                pack_f16x2(acc[i][j][2], acc[i][j][3]);
        }
    }
}

// ============== K2: logits, softmax, z — 64-row tiles, 4 CTAs/SM (R13) ==============
#define K2_AST  196
#define K2_SA   0         // 64*196 = 12544 w
#define K2_SY   12544     // 384 w
#define K2_LOG  12928     // 64
#define K2_EX   12992     // 64
#define K2_AL   13056     // 64
#define K2_WORDS 13120
#define K2_BYTES (K2_WORDS * 4)   // 52,480 B

__global__ __launch_bounds__(256, 4)
void k2_attn(const float* __restrict__ x_nei_rel,
             const float* __restrict__ x_nei_node)
{
    extern __shared__ float sm[];
    const uint32_t sb = smem_u32(sm);
    float*  sA  = sm + K2_SA;
    __half* sYh = (__half*)(sm + K2_SY);
    float*  sLog= sm + K2_LOG;
    float*  sE  = sm + K2_EX;
    float*  sAl = sm + K2_AL;
    const uint32_t aU = sb + K2_SA * 4, yU = sb + K2_SY * 4;

    const int tid = threadIdx.x;
    const int b = blockIdx.y, nc = blockIdx.x;
    const size_t row0  = (size_t)b * 512 + (size_t)nc * 64;
    const int    nbase = b * 32 + nc * 4;

    {
        const float4* rp = (const float4*)(x_nei_rel + row0 * 64);
        #pragma unroll
        for (int it = 0; it < 4; it++) {
            int idx = tid + it * 256;
            int r = idx >> 4, c = idx & 15;
            cpa16(aU + (uint32_t)(r * K2_AST + c * 4) * 4u, rp + r * 16 + c);
        }
        const float4* np = (const float4*)(x_nei_node + row0 * 128);
        #pragma unroll
        for (int it = 0; it < 2; it++) {
            int idx = tid + it * 256;
            int r = idx >> 3, c = idx & 7;
            cpa16(aU + (uint32_t)(r * K2_AST + 64 + c * 4) * 4u, np + r * 32 + c);
        }
        if (tid < 96)
            cpa16(yU + (uint32_t)tid * 16u, g_y16 + (size_t)nbase * 192 + tid * 8);
        cp_commit();
        #pragma unroll
        for (int it = 0; it < 6; it++) {
            int idx = tid + it * 256;
            int r = idx / 24, c = idx - r * 24;
            cpa16(aU + (uint32_t)(r * K2_AST + 96 + c * 4) * 4u, np + r * 32 + 8 + c);
        }
        cp_commit();
    }

    const int r = tid >> 2, h = tid & 3;
    float s = 0.f;
    cp_wait<1>();
    __syncthreads();
    {
        const float*  ar = sA + r * K2_AST + h * 24;
        const __half* yr = sYh + (r >> 4) * 192 + h * 24;
        #pragma unroll
        for (int kk = 0; kk < 12; kk++) {
            float2 a2 = *(const float2*)(ar + 2 * kk);
            float2 yf = __half22float2(*(const __half2*)(yr + 2 * kk));
            s += a2.x * yf.x + a2.y * yf.y;
        }
    }
    cp_wait<0>();
    __syncthreads();
    {
        const float*  ar = sA + r * K2_AST + 96 + h * 24;
        const __half* yr = sYh + (r >> 4) * 192 + 96 + h * 24;
        #pragma unroll
        for (int kk = 0; kk < 12; kk++) {
            float2 a2 = *(const float2*)(ar + 2 * kk);
            float2 yf = __half22float2(*(const __half2*)(yr + 2 * kk));
            s += a2.x * yf.x + a2.y * yf.y;
        }
    }
    s += shflx(s, 1);
    s += shflx(s, 2);
    if (h == 0) sLog[r] = s * 0.08838834764831845f;
    __syncthreads();

    float e = 0.f;
    if (tid < 64) {
        int base = tid & ~15;
        float m = -1e30f;
        #pragma unroll
        for (int q = 0; q < 16; q++) m = fmaxf(m, sLog[base + q]);
        e = __expf(sLog[tid] - m);
        sE[tid] = e;
    }
    __syncthreads();
    if (tid < 64) {
        int base = tid & ~15;
        float den = 0.f;
        #pragma unroll
        for (int q = 0; q < 16; q++) den += sE[base + q];
        sAl[tid] = e / den;
    }
    __syncthreads();

    #pragma unroll
    for (int p = 0; p < 2; p++) {
        int u = tid + 256 * p;
        if (u < 384) {
            int n = u / 96, dp = u - n * 96;
            const float* ap = sA + (n * 16) * K2_AST + 2 * dp;
            const float* al = sAl + n * 16;
            float z0 = 0.f, z1 = 0.f;
            #pragma unroll
            for (int q = 0; q < 16; q++) {
                float2 av = *(const float2*)(ap + q * K2_AST);
                float  a  = al[q];
                z0 += a * av.x;
                z1 += a * av.y;
            }
            *(uint32_t*)(g_z16 + (size_t)(nbase + n) * 192 + 2 * dp) = pack_f16x2(z0, z1);
        }
    }
}

// ============================ K3: out = z @ W^T + b ============================
// 256 CTAs x 64 rows. Pure cp.async, split along K: group0 = k 0..95 (z+W), group1 = k 96..191.
#define K3_ZH   0         // 64*400 = 25600 B
#define K3_WH   25600     // 128*400 = 51200 B
#define K3_BYTES 76800

__global__ __launch_bounds__(256, 2)
void k3_out(const float* __restrict__ W1_b,
            float* __restrict__ out)
{
    extern __shared__ float sm[];
    const uint32_t sb = smem_u32(sm);
    const int tid = threadIdx.x;
    const int wid = tid >> 5, lid = tid & 31;
    const int g = lid >> 2, t4 = lid & 3;
    const int sel = lid >> 3, lr = lid & 7;
    const int wm = wid >> 2, wn = wid & 3;
    const __half* zp = g_z16 + (size_t)blockIdx.x * 64 * 192;

    // group 0: k 0..95
    #pragma unroll
    for (int it = 0; it < 3; it++) {
        int idx = tid + it * 256;                 // 768: r*12 + c
        int r = idx / 12, c = idx - r * 12;
        cpa16(sb + K3_ZH + (uint32_t)(r * 400 + c * 16), zp + r * 192 + c * 8);
    }
    #pragma unroll
    for (int it = 0; it < 6; it++) {
        int idx = tid + it * 256;                 // 1536: r*12 + c
        int r = idx / 12, c = idx - r * 12;
        cpa16(sb + K3_WH + (uint32_t)(r * 400 + c * 16), g_w16 + r * 192 + c * 8);
    }
    cp_commit();
    // group 1: k 96..191
    #pragma unroll
    for (int it = 0; it < 3; it++) {
        int idx = tid + it * 256;
        int r = idx / 12, c = idx - r * 12;
        cpa16(sb + K3_ZH + (uint32_t)(r * 400 + 192 + c * 16), zp + r * 192 + 96 + c * 8);
    }
    #pragma unroll
    for (int it = 0; it < 6; it++) {
        int idx = tid + it * 256;
        int r = idx / 12, c = idx - r * 12;
        cpa16(sb + K3_WH + (uint32_t)(r * 400 + 192 + c * 16), g_w16 + r * 192 + 96 + c * 8);
    }
    cp_commit();

    uint32_t aA[2], bA[2];
    #pragma unroll
    for (int i = 0; i < 2; i++)
        aA[i] = sb + K3_ZH + (uint32_t)(wm * 32 + i * 16 + (sel & 1) * 8 + lr) * 400u
                + (uint32_t)(sel >> 1) * 16u;
    #pragma unroll
    for (int jp = 0; jp < 2; jp++)
        bA[jp] = sb + K3_WH + (uint32_t)(wn * 32 + jp * 16 + (sel >> 1) * 8 + lr) * 400u
                 + (uint32_t)(sel & 1) * 16u;

    float acc[2][4][4];
    #pragma unroll
    for (int i = 0; i < 2; i++)
        #pragma unroll
        for (int j = 0; j < 4; j++)
            #pragma unroll
            for (int q = 0; q < 4; q++) acc[i][j][q] = 0.f;

    cp_wait<1>();
    __syncthreads();
    #pragma unroll
    for (int ks = 0; ks < 6; ks++) {
        uint32_t a0[4], a1[4], b0[4], b1[4];
        ldsm4(a0, aA[0] + ks * 32);
        ldsm4(a1, aA[1] + ks * 32);
        ldsm4(b0, bA[0] + ks * 32);
        ldsm4(b1, bA[1] + ks * 32);
        mma_f16(acc[0][0], a0, b0[0], b0[1]);
        mma_f16(acc[0][1], a0, b0[2], b0[3]);
        mma_f16(acc[0][2], a0, b1[0], b1[1]);
        mma_f16(acc[0][3], a0, b1[2], b1[3]);
        mma_f16(acc[1][0], a1, b0[0], b0[1]);
        mma_f16(acc[1][1], a1, b0[2], b0[3]);
        mma_f16(acc[1][2], a1, b1[0], b1[1]);
        mma_f16(acc[1][3], a1, b1[2], b1[3]);
    }
    cp_wait<0>();
    __syncthreads();
    #pragma unroll
    for (int ks = 6; ks < 12; ks++) {
        uint32_t a0[4], a1[4], b0[4], b1[4];
        ldsm4(a0, aA[0] + ks * 32);
        ldsm4(a1, aA[1] + ks * 32);
        ldsm4(b0, bA[0] + ks * 32);
        ldsm4(b1, bA[1] + ks * 32);
        mma_f16(acc[0][0], a0, b0[0], b0[1]);
        mma_f16(acc[0][1], a0, b0[2], b0[3]);
        mma_f16(acc[0][2], a0, b1[0], b1[1]);
        mma_f16(acc[0][3], a0, b1[2], b1[3]);
        mma_f16(acc[1][0], a1, b0[0], b0[1]);
        mma_f16(acc[1][1], a1, b0[2], b0[3]);
        mma_f16(acc[1][2], a1, b1[0], b1[1]);
        mma_f16(acc[1][3], a1, b1[2], b1[3]);
    }

    #pragma unroll
    for (int i = 0; i < 2; i++) {
        int row = blockIdx.x * 64 + wm * 32 + i * 16 + g;
        #pragma unroll
        for (int j = 0; j < 4; j++) {
            int col = wn * 32 + j * 8 + 2 * t4;
            float b0 = __ldg(W1_b + col), b1 = __ldg(W1_b + col + 1);
            float2 w0 = { acc[i][j][0] + b0, acc[i][j][1] + b1 };
            float2 w1 = { acc[i][j][2] + b0, acc[i][j][3] + b1 };
            *(float2*)(out + (size_t)row * 128 + col)       = w0;
            *(float2*)(out + (size_t)(row + 8) * 128 + col) = w1;
        }
    }
}

extern "C" void kernel_launch(void* const* d_in, const int* in_sizes, int n_in,
                              void* d_out, int out_size)
{
    const float* x          = (const float*)d_in[0];
    const float* x_nei_rel  = (const float*)d_in[1];
    const float* x_nei_node = (const float*)d_in[2];
    const float* W1_w       = (const float*)d_in[3];
    const float* W1_b       = (const float*)d_in[4];
    float* out = (float*)d_out;

    cudaFuncSetAttribute(k1_y,    cudaFuncAttributeMaxDynamicSharedMemorySize, K1_BYTES);
    cudaFuncSetAttribute(k2_attn, cudaFuncAttributeMaxDynamicSharedMemorySize, K2_BYTES);
    cudaFuncSetAttribute(k3_out,  cudaFuncAttributeMaxDynamicSharedMemorySize, K3_BYTES);

    k0_cvt<<<1024, 256>>>(W1_w, x);
    k1_y<<<256, 256, K1_BYTES>>>(0);
    k2_attn<<<dim3(8, 512), 256, K2_BYTES>>>(x_nei_rel, x_nei_node);
    k3_out<<<256, 256, K3_BYTES>>>(W1_b, out);
}

// round 15
// speedup vs baseline: 1.0106x; 1.0106x over previous
#include <cuda_runtime.h>
#include <cuda_fp16.h>
#include <cstdint>

// NeiAttention, 3-kernel form (round 15 = R13 with N-split K1/K3 for 4 CTAs/SM).
// K1: y = x @ W      grid (256,2): 64 rows x 96 cols per CTA, half of W staged
// K2: logits/softmax/z   unchanged from R13 (64-row tiles, 4 CTAs/SM)
// K3: out = z @ W^T + b  grid (256,2): 64 rows x 64 cols per CTA, half of W rows staged

__device__ __half g_y16[16384 * 192];
__device__ __half g_z16[16384 * 192];

__device__ __forceinline__ uint32_t smem_u32(const void* p) {
    uint32_t a;
    asm("{ .reg .u64 t; cvta.to.shared.u64 t, %1; cvt.u32.u64 %0, t; }" : "=r"(a) : "l"(p));
    return a;
}
__device__ __forceinline__ uint32_t pack_f16x2(float lo, float hi) {
    uint32_t r;
    asm("cvt.rn.f16x2.f32 %0, %1, %2;" : "=r"(r) : "f"(hi), "f"(lo));
    return r;
}
__device__ __forceinline__ void ldsm4(uint32_t r[4], uint32_t addr) {
    asm volatile("ldmatrix.sync.aligned.m8n8.x4.shared.b16 {%0,%1,%2,%3}, [%4];"
                 : "=r"(r[0]), "=r"(r[1]), "=r"(r[2]), "=r"(r[3]) : "r"(addr));
}
__device__ __forceinline__ void ldsm4t(uint32_t r[4], uint32_t addr) {
    asm volatile("ldmatrix.sync.aligned.m8n8.x4.trans.shared.b16 {%0,%1,%2,%3}, [%4];"
                 : "=r"(r[0]), "=r"(r[1]), "=r"(r[2]), "=r"(r[3]) : "r"(addr));
}
__device__ __forceinline__ void mma_f16(float d[4], const uint32_t a[4],
                                        uint32_t b0, uint32_t b1) {
    asm volatile(
        "mma.sync.aligned.m16n8k16.row.col.f32.f16.f16.f32 "
        "{%0,%1,%2,%3}, {%4,%5,%6,%7}, {%8,%9}, {%0,%1,%2,%3};"
        : "+f"(d[0]), "+f"(d[1]), "+f"(d[2]), "+f"(d[3])
        : "r"(a[0]), "r"(a[1]), "r"(a[2]), "r"(a[3]), "r"(b0), "r"(b1));
}
__device__ __forceinline__ void cpa16(uint32_t dst, const void* src) {
    asm volatile("cp.async.cg.shared.global [%0], [%1], 16;" :: "r"(dst), "l"(src));
}
__device__ __forceinline__ void cp_commit() { asm volatile("cp.async.commit_group;" ::: "memory"); }
template <int N>
__device__ __forceinline__ void cp_wait() { asm volatile("cp.async.wait_group %0;" :: "n"(N) : "memory"); }
__device__ __forceinline__ float shflx(float v, int m) { return __shfl_xor_sync(0xffffffffu, v, m); }

// ============================ K1: y = x @ W ============================
// grid (256, 2): blockIdx.x = 64-row tile, blockIdx.y = h (k'-cols 96h..96h+95).
// 8 warps, warp grid 4(m) x 2(n): warp tile 16 rows x 48 cols.
#define K1_XH   0         // x fp16: 64 rows x 272 B = 17408
#define K1_WH   17408     // W half fp16: 128 d-rows x 208 B = 26624
#define K1_BYTES 44032    // -> 4 CTAs/SM

__global__ __launch_bounds__(256, 4)
void k1_y(const float* __restrict__ x, const float* __restrict__ W1_w)
{
    extern __shared__ float sm[];
    const uint32_t sb = smem_u32(sm);
    const int tid = threadIdx.x;
    const int wid = tid >> 5, lid = tid & 31;
    const int g = lid >> 2, t4 = lid & 3;
    const int sel = lid >> 3, lr = lid & 7;
    const int wm = wid >> 1, wn = wid & 1;
    const int h  = blockIdx.y;                   // col half

    // stage x tile (64 rows x 128 d, fp32 -> fp16, stride 272 B)
    {
        const float4* xp = (const float4*)(x + (size_t)blockIdx.x * 64 * 128);
        #pragma unroll
        for (int it = 0; it < 8; it++) {
            int idx = tid + it * 256;            // r*32 + c
            int r = idx >> 5, c = idx & 31;
            float4 v = xp[idx];
            uint2 w;
            w.x = pack_f16x2(v.x, v.y);
            w.y = pack_f16x2(v.z, v.w);
            *(uint2*)((char*)sm + K1_XH + r * 272 + c * 8) = w;
        }
    }
    // stage W half: cols [96h, 96h+96) of [128][192], fp32 -> fp16, stride 208 B
    {
        #pragma unroll
        for (int it = 0; it < 12; it++) {
            int idx = tid + it * 256;            // 3072: r*24 + c
            int r = idx / 24, c = idx - r * 24;
            float4 v = *(const float4*)(W1_w + (size_t)r * 192 + h * 96 + c * 4);
            uint2 w;
            w.x = pack_f16x2(v.x, v.y);
            w.y = pack_f16x2(v.z, v.w);
            *(uint2*)((char*)sm + K1_WH + r * 208 + c * 8) = w;
        }
    }
    __syncthreads();

    // A frag: rows wm*16 .. +15
    const uint32_t aA = sb + K1_XH + (uint32_t)(wm * 16 + (sel & 1) * 8 + lr) * 272u
                        + (uint32_t)(sel >> 1) * 16u;
    // B trans frags (local cols wn*48 + jp*16)
    const int drow = (lid & 7) + ((lid >> 3) & 1) * 8;
    const int kgrp = lid >> 4;
    uint32_t bT[3];
    #pragma unroll
    for (int jp = 0; jp < 3; jp++)
        bT[jp] = sb + K1_WH + (uint32_t)drow * 208u
                 + (uint32_t)(wn * 48 + jp * 16 + kgrp * 8) * 2u;

    float acc[6][4];
    #pragma unroll
    for (int j = 0; j < 6; j++)
        #pragma unroll
        for (int q = 0; q < 4; q++) acc[j][q] = 0.f;

    #pragma unroll
    for (int ks = 0; ks < 8; ks++) {             // K = 128 over d
        uint32_t a[4];
        ldsm4(a, aA + ks * 32);                  // +16 halves along d
        #pragma unroll
        for (int jp = 0; jp < 3; jp++) {
            uint32_t bt[4];
            ldsm4t(bt, bT[jp] + ks * 3328);      // +16 d-rows * 208 B
            mma_f16(acc[2 * jp],     a, bt[0], bt[1]);
            mma_f16(acc[2 * jp + 1], a, bt[2], bt[3]);
        }
    }

    // write y fp16 (global cols 96h + local)
    {
        int row = blockIdx.x * 64 + wm * 16 + g;
        #pragma unroll
        for (int j = 0; j < 6; j++) {
            int col = h * 96 + wn * 48 + j * 8 + 2 * t4;
            *(uint32_t*)(g_y16 + (size_t)row * 192 + col) =
                pack_f16x2(acc[j][0], acc[j][1]);
            *(uint32_t*)(g_y16 + (size_t)(row + 8) * 192 + col) =
                pack_f16x2(acc[j][2], acc[j][3]);
        }
    }
}

// ============== K2: logits, softmax, z — 64-row tiles, 4 CTAs/SM (R13, unchanged) ==============
#define K2_AST  196
#define K2_SA   0         // 64*196 = 12544 w
#define K2_SY   12544     // 384 w
#define K2_LOG  12928     // 64
#define K2_EX   12992     // 64
#define K2_AL   13056     // 64
#define K2_WORDS 13120
#define K2_BYTES (K2_WORDS * 4)   // 52,480 B

__global__ __launch_bounds__(256, 4)
void k2_attn(const float* __restrict__ x_nei_rel,
             const float* __restrict__ x_nei_node)
{
    extern __shared__ float sm[];
    const uint32_t sb = smem_u32(sm);
    float*  sA  = sm + K2_SA;
    __half* sYh = (__half*)(sm + K2_SY);
    float*  sLog= sm + K2_LOG;
    float*  sE  = sm + K2_EX;
    float*  sAl = sm + K2_AL;
    const uint32_t aU = sb + K2_SA * 4, yU = sb + K2_SY * 4;

    const int tid = threadIdx.x;
    const int b = blockIdx.y, nc = blockIdx.x;
    const size_t row0  = (size_t)b * 512 + (size_t)nc * 64;
    const int    nbase = b * 32 + nc * 4;

    {
        const float4* rp = (const float4*)(x_nei_rel + row0 * 64);
        #pragma unroll
        for (int it = 0; it < 4; it++) {
            int idx = tid + it * 256;
            int r = idx >> 4, c = idx & 15;
            cpa16(aU + (uint32_t)(r * K2_AST + c * 4) * 4u, rp + r * 16 + c);
        }
        const float4* np = (const float4*)(x_nei_node + row0 * 128);
        #pragma unroll
        for (int it = 0; it < 2; it++) {
            int idx = tid + it * 256;
            int r = idx >> 3, c = idx & 7;
            cpa16(aU + (uint32_t)(r * K2_AST + 64 + c * 4) * 4u, np + r * 32 + c);
        }
        if (tid < 96)
            cpa16(yU + (uint32_t)tid * 16u, g_y16 + (size_t)nbase * 192 + tid * 8);
        cp_commit();
        #pragma unroll
        for (int it = 0; it < 6; it++) {
            int idx = tid + it * 256;
            int r = idx / 24, c = idx - r * 24;
            cpa16(aU + (uint32_t)(r * K2_AST + 96 + c * 4) * 4u, np + r * 32 + 8 + c);
        }
        cp_commit();
    }

    const int r = tid >> 2, h = tid & 3;
    float s = 0.f;
    cp_wait<1>();
    __syncthreads();
    {
        const float*  ar = sA + r * K2_AST + h * 24;
        const __half* yr = sYh + (r >> 4) * 192 + h * 24;
        #pragma unroll
        for (int kk = 0; kk < 12; kk++) {
            float2 a2 = *(const float2*)(ar + 2 * kk);
            float2 yf = __half22float2(*(const __half2*)(yr + 2 * kk));
            s += a2.x * yf.x + a2.y * yf.y;
        }
    }
    cp_wait<0>();
    __syncthreads();
    {
        const float*  ar = sA + r * K2_AST + 96 + h * 24;
        const __half* yr = sYh + (r >> 4) * 192 + 96 + h * 24;
        #pragma unroll
        for (int kk = 0; kk < 12; kk++) {
            float2 a2 = *(const float2*)(ar + 2 * kk);
            float2 yf = __half22float2(*(const __half2*)(yr + 2 * kk));
            s += a2.x * yf.x + a2.y * yf.y;
        }
    }
    s += shflx(s, 1);
    s += shflx(s, 2);
    if (h == 0) sLog[r] = s * 0.08838834764831845f;   // 1/sqrt(128)
    __syncthreads();

    float e = 0.f;
    if (tid < 64) {
        int base = tid & ~15;
        float m = -1e30f;
        #pragma unroll
        for (int q = 0; q < 16; q++) m = fmaxf(m, sLog[base + q]);
        e = __expf(sLog[tid] - m);
        sE[tid] = e;
    }
    __syncthreads();
    if (tid < 64) {
        int base = tid & ~15;
        float den = 0.f;
        #pragma unroll
        for (int q = 0; q < 16; q++) den += sE[base + q];
        sAl[tid] = e / den;
    }
    __syncthreads();

    #pragma unroll
    for (int p = 0; p < 2; p++) {
        int u = tid + 256 * p;
        if (u < 384) {
            int n = u / 96, dp = u - n * 96;
            const float* ap = sA + (n * 16) * K2_AST + 2 * dp;
            const float* al = sAl + n * 16;
            float z0 = 0.f, z1 = 0.f;
            #pragma unroll
            for (int q = 0; q < 16; q++) {
                float2 av = *(const float2*)(ap + q * K2_AST);
                float  a  = al[q];
                z0 += a * av.x;
                z1 += a * av.y;
            }
            *(uint32_t*)(g_z16 + (size_t)(nbase + n) * 192 + 2 * dp) = pack_f16x2(z0, z1);
        }
    }
}

// ============================ K3: out = z @ W^T + b ============================
// grid (256, 2): blockIdx.x = 64-row tile, blockIdx.y = h (out cols 64h..64h+63).
// 8 warps, warp grid 4(m) x 2(n): warp tile 16 rows x 32 cols.
#define K3_ZH   0         // z fp16: 64 rows x 400 B = 25600
#define K3_WH   25600     // W rows [64h,64h+64) fp16: 64 x 400 B = 25600
#define K3_BYTES 51200    // -> 4 CTAs/SM

__global__ __launch_bounds__(256, 4)
void k3_out(const float* __restrict__ W1_w,
            const float* __restrict__ W1_b,
            float* __restrict__ out)
{
    extern __shared__ float sm[];
    const uint32_t sb = smem_u32(sm);
    const int tid = threadIdx.x;
    const int wid = tid >> 5, lid = tid & 31;
    const int g = lid >> 2, t4 = lid & 3;
    const int sel = lid >> 3, lr = lid & 7;
    const int wm = wid >> 1, wn = wid & 1;
    const int h  = blockIdx.y;

    // stage z rows (fp16) via cp.async
    {
        const __half* zp = g_z16 + (size_t)blockIdx.x * 64 * 192;
        #pragma unroll
        for (int it = 0; it < 6; it++) {
            int idx = tid + it * 256;            // 1536: r*24 + c
            int r = idx / 24, c = idx - r * 24;
            cpa16(sb + K3_ZH + (uint32_t)(r * 400 + c * 16), zp + r * 192 + c * 8);
        }
        cp_commit();
    }
    // stage W rows [64h, 64h+64) fp32 -> fp16 (overlaps z flight)
    {
        #pragma unroll
        for (int it = 0; it < 12; it++) {
            int idx = tid + it * 256;            // 3072: r*48 + c
            int r = idx / 48, c = idx - r * 48;
            float4 v = *(const float4*)(W1_w + (size_t)(h * 64 + r) * 192 + c * 4);
            uint2 w;
            w.x = pack_f16x2(v.x, v.y);
            w.y = pack_f16x2(v.z, v.w);
            *(uint2*)((char*)sm + K3_WH + r * 400 + c * 8) = w;
        }
    }
    cp_wait<0>();
    __syncthreads();

    const uint32_t aA = sb + K3_ZH + (uint32_t)(wm * 16 + (sel & 1) * 8 + lr) * 400u
                        + (uint32_t)(sel >> 1) * 16u;
    uint32_t bA[2];
    #pragma unroll
    for (int jp = 0; jp < 2; jp++)
        bA[jp] = sb + K3_WH + (uint32_t)(wn * 32 + jp * 16 + (sel >> 1) * 8 + lr) * 400u
                 + (uint32_t)(sel & 1) * 16u;

    float acc[4][4];
    #pragma unroll
    for (int j = 0; j < 4; j++)
        #pragma unroll
        for (int q = 0; q < 4; q++) acc[j][q] = 0.f;

    #pragma unroll
    for (int ks = 0; ks < 12; ks++) {            // K = 192
        uint32_t a[4], b0[4], b1[4];
        ldsm4(a, aA + ks * 32);
        ldsm4(b0, bA[0] + ks * 32);
        ldsm4(b1, bA[1] + ks * 32);
        mma_f16(acc[0], a, b0[0], b0[1]);
        mma_f16(acc[1], a, b0[2], b0[3]);
        mma_f16(acc[2], a, b1[0], b1[1]);
        mma_f16(acc[3], a, b1[2], b1[3]);
    }

    // store out + bias (global cols 64h + local)
    {
        int row = blockIdx.x * 64 + wm * 16 + g;
        #pragma unroll
        for (int j = 0; j < 4; j++) {
            int col = h * 64 + wn * 32 + j * 8 + 2 * t4;
            float b0 = __ldg(W1_b + col), b1 = __ldg(W1_b + col + 1);
            float2 w0 = { acc[j][0] + b0, acc[j][1] + b1 };
            float2 w1 = { acc[j][2] + b0, acc[j][3] + b1 };
            *(float2*)(out + (size_t)row * 128 + col)       = w0;
            *(float2*)(out + (size_t)(row + 8) * 128 + col) = w1;
        }
    }
}

extern "C" void kernel_launch(void* const* d_in, const int* in_sizes, int n_in,
                              void* d_out, int out_size)
{
    const float* x          = (const float*)d_in[0];
    const float* x_nei_rel  = (const float*)d_in[1];
    const float* x_nei_node = (const float*)d_in[2];
    const float* W1_w       = (const float*)d_in[3];
    const float* W1_b       = (const float*)d_in[4];
    float* out = (float*)d_out;

    cudaFuncSetAttribute(k1_y,    cudaFuncAttributeMaxDynamicSharedMemorySize, K1_BYTES);
    cudaFuncSetAttribute(k2_attn, cudaFuncAttributeMaxDynamicSharedMemorySize, K2_BYTES);
    cudaFuncSetAttribute(k3_out,  cudaFuncAttributeMaxDynamicSharedMemorySize, K3_BYTES);

    k1_y<<<dim3(256, 2), 256, K1_BYTES>>>(x, W1_w);
    k2_attn<<<dim3(8, 512), 256, K2_BYTES>>>(x_nei_rel, x_nei_node);
    k3_out<<<dim3(256, 2), 256, K3_BYTES>>>(W1_w, W1_b, out);
}

// round 16
// speedup vs baseline: 1.1188x; 1.1071x over previous
#include <cuda_runtime.h>
#include <cuda_fp16.h>
#include <cstdint>

// NeiAttention, 3-kernel form (round 16 = R13 + Programmatic Dependent Launch overlap).
// K1: y = x @ W            fp16 MMA (R13 form) + PDL trigger
// K2: logits/softmax/z     A cp.asyncs issued pre-gridDepSync (overlap K1), y after; + trigger
// K3: out = z @ W^T + b    W staged pre-gridDepSync (overlap K2), z after

__device__ __half g_y16[16384 * 192];
__device__ __half g_z16[16384 * 192];

__device__ __forceinline__ uint32_t smem_u32(const void* p) {
    uint32_t a;
    asm("{ .reg .u64 t; cvta.to.shared.u64 t, %1; cvt.u32.u64 %0, t; }" : "=r"(a) : "l"(p));
    return a;
}
__device__ __forceinline__ uint32_t pack_f16x2(float lo, float hi) {
    uint32_t r;
    asm("cvt.rn.f16x2.f32 %0, %1, %2;" : "=r"(r) : "f"(hi), "f"(lo));
    return r;
}
__device__ __forceinline__ void ldsm4(uint32_t r[4], uint32_t addr) {
    asm volatile("ldmatrix.sync.aligned.m8n8.x4.shared.b16 {%0,%1,%2,%3}, [%4];"
                 : "=r"(r[0]), "=r"(r[1]), "=r"(r[2]), "=r"(r[3]) : "r"(addr));
}
__device__ __forceinline__ void ldsm4t(uint32_t r[4], uint32_t addr) {
    asm volatile("ldmatrix.sync.aligned.m8n8.x4.trans.shared.b16 {%0,%1,%2,%3}, [%4];"
                 : "=r"(r[0]), "=r"(r[1]), "=r"(r[2]), "=r"(r[3]) : "r"(addr));
}
__device__ __forceinline__ void mma_f16(float d[4], const uint32_t a[4],
                                        uint32_t b0, uint32_t b1) {
    asm volatile(
        "mma.sync.aligned.m16n8k16.row.col.f32.f16.f16.f32 "
        "{%0,%1,%2,%3}, {%4,%5,%6,%7}, {%8,%9}, {%0,%1,%2,%3};"
        : "+f"(d[0]), "+f"(d[1]), "+f"(d[2]), "+f"(d[3])
        : "r"(a[0]), "r"(a[1]), "r"(a[2]), "r"(a[3]), "r"(b0), "r"(b1));
}
__device__ __forceinline__ void cpa16(uint32_t dst, const void* src) {
    asm volatile("cp.async.cg.shared.global [%0], [%1], 16;" :: "r"(dst), "l"(src));
}
__device__ __forceinline__ void cp_commit() { asm volatile("cp.async.commit_group;" ::: "memory"); }
template <int N>
__device__ __forceinline__ void cp_wait() { asm volatile("cp.async.wait_group %0;" :: "n"(N) : "memory"); }
__device__ __forceinline__ float shflx(float v, int m) { return __shfl_xor_sync(0xffffffffu, v, m); }

// ============================ K1: y = x @ W (R13 form) ============================
#define K1_XH   0         // 64*68  = 4352 w
#define K1_WH   4352      // 128*100 = 12800 w
#define K1_WORDS 17152
#define K1_BYTES (K1_WORDS * 4)   // 68,608 B

__global__ __launch_bounds__(256, 2)
void k1_y(const float* __restrict__ x, const float* __restrict__ W1_w)
{
    extern __shared__ float sm[];
    const uint32_t sb = smem_u32(sm);
    const int tid = threadIdx.x;
    const int wid = tid >> 5, lid = tid & 31;
    const int g = lid >> 2, t4 = lid & 3;
    const int sel = lid >> 3, lr = lid & 7;
    const int wm = wid >> 2, wn = wid & 3;

    // stage x tile (64 rows, fp16, stride 68 words)
    {
        const float4* xp = (const float4*)(x + (size_t)blockIdx.x * 64 * 128);
        #pragma unroll
        for (int it = 0; it < 8; it++) {
            int idx = tid + it * 256;
            int r = idx >> 5, c = idx & 31;
            float4 v = xp[idx];
            uint2 w;
            w.x = pack_f16x2(v.x, v.y);
            w.y = pack_f16x2(v.z, v.w);
            *(uint2*)((uint32_t*)sm + K1_XH + r * 68 + 2 * c) = w;
        }
    }
    // stage W natural [d][k'] fp16 (stride 100 words)
    {
        const float4* Wv = (const float4*)W1_w;
        #pragma unroll
        for (int it = 0; it < 24; it++) {
            int idx = tid + it * 256;
            int d = idx / 48, c = idx - d * 48;
            float4 v = Wv[idx];
            uint2 w;
            w.x = pack_f16x2(v.x, v.y);
            w.y = pack_f16x2(v.z, v.w);
            *(uint2*)((uint32_t*)sm + K1_WH + d * 100 + 2 * c) = w;
        }
    }
    __syncthreads();

    uint32_t aA[2];
    #pragma unroll
    for (int i = 0; i < 2; i++)
        aA[i] = sb + K1_XH * 4 + (uint32_t)(wm * 32 + i * 16 + (sel & 1) * 8 + lr) * 272u
                + (uint32_t)(sel >> 1) * 16u;
    const int drow = (lid & 7) + ((lid >> 3) & 1) * 8;
    const int kgrp = lid >> 4;
    uint32_t bT[3];
    #pragma unroll
    for (int jp = 0; jp < 3; jp++)
        bT[jp] = sb + K1_WH * 4 + (uint32_t)drow * 400u
                 + (uint32_t)(wn * 48 + jp * 16 + kgrp * 8) * 2u;

    float acc[2][6][4];
    #pragma unroll
    for (int i = 0; i < 2; i++)
        #pragma unroll
        for (int j = 0; j < 6; j++)
            #pragma unroll
            for (int q = 0; q < 4; q++) acc[i][j][q] = 0.f;

    #pragma unroll
    for (int ks = 0; ks < 8; ks++) {
        uint32_t a0[4], a1[4];
        ldsm4(a0, aA[0] + ks * 32);
        ldsm4(a1, aA[1] + ks * 32);
        #pragma unroll
        for (int jp = 0; jp < 3; jp++) {
            uint32_t bt[4];
            ldsm4t(bt, bT[jp] + ks * 6400);
            mma_f16(acc[0][2 * jp],     a0, bt[0], bt[1]);
            mma_f16(acc[0][2 * jp + 1], a0, bt[2], bt[3]);
            mma_f16(acc[1][2 * jp],     a1, bt[0], bt[1]);
            mma_f16(acc[1][2 * jp + 1], a1, bt[2], bt[3]);
        }
    }

    #pragma unroll
    for (int i = 0; i < 2; i++) {
        int row = blockIdx.x * 64 + wm * 32 + i * 16 + g;
        #pragma unroll
        for (int j = 0; j < 6; j++) {
            int col = wn * 48 + j * 8 + 2 * t4;
            *(uint32_t*)(g_y16 + (size_t)row * 192 + col) =
                pack_f16x2(acc[i][j][0], acc[i][j][1]);
            *(uint32_t*)(g_y16 + (size_t)(row + 8) * 192 + col) =
                pack_f16x2(acc[i][j][2], acc[i][j][3]);
        }
    }
    cudaTriggerProgrammaticLaunchCompletion();
}

// ============== K2: logits, softmax, z — 64-row tiles, 4 CTAs/SM, PDL ==============
#define K2_AST  196
#define K2_SA   0         // 64*196 = 12544 w
#define K2_SY   12544     // 384 w
#define K2_LOG  12928     // 64
#define K2_EX   12992     // 64
#define K2_AL   13056     // 64
#define K2_WORDS 13120
#define K2_BYTES (K2_WORDS * 4)   // 52,480 B

__global__ __launch_bounds__(256, 4)
void k2_attn(const float* __restrict__ x_nei_rel,
             const float* __restrict__ x_nei_node)
{
    extern __shared__ float sm[];
    const uint32_t sb = smem_u32(sm);
    float*  sA  = sm + K2_SA;
    __half* sYh = (__half*)(sm + K2_SY);
    float*  sLog= sm + K2_LOG;
    float*  sE  = sm + K2_EX;
    float*  sAl = sm + K2_AL;
    const uint32_t aU = sb + K2_SA * 4, yU = sb + K2_SY * 4;

    const int tid = threadIdx.x;
    const int b = blockIdx.y, nc = blockIdx.x;
    const size_t row0  = (size_t)b * 512 + (size_t)nc * 64;
    const int    nbase = b * 32 + nc * 4;

    // ---- A streaming: issued BEFORE gridDepSync (independent of K1) ----
    {
        const float4* rp = (const float4*)(x_nei_rel + row0 * 64);
        #pragma unroll
        for (int it = 0; it < 4; it++) {
            int idx = tid + it * 256;
            int r = idx >> 4, c = idx & 15;
            cpa16(aU + (uint32_t)(r * K2_AST + c * 4) * 4u, rp + r * 16 + c);
        }
        const float4* np = (const float4*)(x_nei_node + row0 * 128);
        #pragma unroll
        for (int it = 0; it < 2; it++) {
            int idx = tid + it * 256;
            int r = idx >> 3, c = idx & 7;
            cpa16(aU + (uint32_t)(r * K2_AST + 64 + c * 4) * 4u, np + r * 32 + c);
        }
        #pragma unroll
        for (int it = 0; it < 6; it++) {
            int idx = tid + it * 256;
            int r = idx / 24, c = idx - r * 24;
            cpa16(aU + (uint32_t)(r * K2_AST + 96 + c * 4) * 4u, np + r * 32 + 8 + c);
        }
        cp_commit();
    }

    // ---- wait for K1's y, then pull it ----
    cudaGridDependencySynchronize();
    if (tid < 96)
        cpa16(yU + (uint32_t)tid * 16u, g_y16 + (size_t)nbase * 192 + tid * 8);
    cp_commit();

    cp_wait<0>();
    __syncthreads();

    // ---- dots: 4 threads per row, full K=192 ----
    const int r = tid >> 2, h = tid & 3;
    float s = 0.f;
    {
        const float*  ar = sA + r * K2_AST + h * 24;
        const __half* yr = sYh + (r >> 4) * 192 + h * 24;
        #pragma unroll
        for (int kk = 0; kk < 12; kk++) {
            float2 a2 = *(const float2*)(ar + 2 * kk);
            float2 yf = __half22float2(*(const __half2*)(yr + 2 * kk));
            s += a2.x * yf.x + a2.y * yf.y;
        }
    }
    {
        const float*  ar = sA + r * K2_AST + 96 + h * 24;
        const __half* yr = sYh + (r >> 4) * 192 + 96 + h * 24;
        #pragma unroll
        for (int kk = 0; kk < 12; kk++) {
            float2 a2 = *(const float2*)(ar + 2 * kk);
            float2 yf = __half22float2(*(const __half2*)(yr + 2 * kk));
            s += a2.x * yf.x + a2.y * yf.y;
        }
    }
    s += shflx(s, 1);
    s += shflx(s, 2);
    if (h == 0) sLog[r] = s * 0.08838834764831845f;   // 1/sqrt(128)
    __syncthreads();

    // ---- softmax over S=16 per node ----
    float e = 0.f;
    if (tid < 64) {
        int base = tid & ~15;
        float m = -1e30f;
        #pragma unroll
        for (int q = 0; q < 16; q++) m = fmaxf(m, sLog[base + q]);
        e = __expf(sLog[tid] - m);
        sE[tid] = e;
    }
    __syncthreads();
    if (tid < 64) {
        int base = tid & ~15;
        float den = 0.f;
        #pragma unroll
        for (int q = 0; q < 16; q++) den += sE[base + q];
        sAl[tid] = e / den;
    }
    __syncthreads();

    // ---- z = sum_s alpha * a -> fp16 ----
    #pragma unroll
    for (int p = 0; p < 2; p++) {
        int u = tid + 256 * p;
        if (u < 384) {
            int n = u / 96, dp = u - n * 96;
            const float* ap = sA + (n * 16) * K2_AST + 2 * dp;
            const float* al = sAl + n * 16;
            float z0 = 0.f, z1 = 0.f;
            #pragma unroll
            for (int q = 0; q < 16; q++) {
                float2 av = *(const float2*)(ap + q * K2_AST);
                float  a  = al[q];
                z0 += a * av.x;
                z1 += a * av.y;
            }
            *(uint32_t*)(g_z16 + (size_t)(nbase + n) * 192 + 2 * dp) = pack_f16x2(z0, z1);
        }
    }
    cudaTriggerProgrammaticLaunchCompletion();
}

// ============================ K3: out = z @ W^T + b, PDL ============================
#define K3_ZH   0         // 64*100 = 6400 w
#define K3_WH   6400      // 128*100 = 12800 w
#define K3_WORDS 19200
#define K3_BYTES (K3_WORDS * 4)   // 76,800 B

__global__ __launch_bounds__(256, 2)
void k3_out(const float* __restrict__ W1_w,
            const float* __restrict__ W1_b,
            float* __restrict__ out)
{
    extern __shared__ float sm[];
    const uint32_t sb = smem_u32(sm);
    const int tid = threadIdx.x;
    const int wid = tid >> 5, lid = tid & 31;
    const int g = lid >> 2, t4 = lid & 3;
    const int sel = lid >> 3, lr = lid & 7;
    const int wm = wid >> 2, wn = wid & 3;

    // ---- W staging (fp32 -> fp16): BEFORE gridDepSync, overlaps K2 tail ----
    {
        const float4* Wv = (const float4*)W1_w;
        #pragma unroll
        for (int it = 0; it < 24; it++) {
            int idx = tid + it * 256;
            int d = idx / 48, c = idx - d * 48;
            float4 v = Wv[idx];
            uint2 w;
            w.x = pack_f16x2(v.x, v.y);
            w.y = pack_f16x2(v.z, v.w);
            *(uint2*)((uint32_t*)sm + K3_WH + d * 100 + 2 * c) = w;
        }
    }

    // ---- wait for K2's z, then pull it ----
    cudaGridDependencySynchronize();
    {
        const __half* zp = g_z16 + (size_t)blockIdx.x * 64 * 192;
        #pragma unroll
        for (int it = 0; it < 6; it++) {
            int idx = tid + it * 256;
            int r = idx / 24, c = idx - r * 24;
            cpa16(sb + K3_ZH * 4 + (uint32_t)(r * 100 + c * 4) * 4u, zp + r * 192 + c * 8);
        }
        cp_commit();
    }
    cp_wait<0>();
    __syncthreads();

    uint32_t aA[2], bA[2];
    #pragma unroll
    for (int i = 0; i < 2; i++)
        aA[i] = sb + K3_ZH * 4 + (uint32_t)(wm * 32 + i * 16 + (sel & 1) * 8 + lr) * 400u
                + (uint32_t)(sel >> 1) * 16u;
    #pragma unroll
    for (int jp = 0; jp < 2; jp++)
        bA[jp] = sb + K3_WH * 4 + (uint32_t)(wn * 32 + jp * 16 + (sel >> 1) * 8 + lr) * 400u
                 + (uint32_t)(sel & 1) * 16u;

    float acc[2][4][4];
    #pragma unroll
    for (int i = 0; i < 2; i++)
        #pragma unroll
        for (int j = 0; j < 4; j++)
            #pragma unroll
            for (int q = 0; q < 4; q++) acc[i][j][q] = 0.f;

    #pragma unroll
    for (int ks = 0; ks < 12; ks++) {
        uint32_t a0[4], a1[4], b0[4], b1[4];
        ldsm4(a0, aA[0] + ks * 32);
        ldsm4(a1, aA[1] + ks * 32);
        ldsm4(b0, bA[0] + ks * 32);
        ldsm4(b1, bA[1] + ks * 32);
        mma_f16(acc[0][0], a0, b0[0], b0[1]);
        mma_f16(acc[0][1], a0, b0[2], b0[3]);
        mma_f16(acc[0][2], a0, b1[0], b1[1]);
        mma_f16(acc[0][3], a0, b1[2], b1[3]);
        mma_f16(acc[1][0], a1, b0[0], b0[1]);
        mma_f16(acc[1][1], a1, b0[2], b0[3]);
        mma_f16(acc[1][2], a1, b1[0], b1[1]);
        mma_f16(acc[1][3], a1, b1[2], b1[3]);
    }

    #pragma unroll
    for (int i = 0; i < 2; i++) {
        int row = blockIdx.x * 64 + wm * 32 + i * 16 + g;
        #pragma unroll
        for (int j = 0; j < 4; j++) {
            int col = wn * 32 + j * 8 + 2 * t4;
            float b0 = __ldg(W1_b + col), b1 = __ldg(W1_b + col + 1);
            float2 w0 = { acc[i][j][0] + b0, acc[i][j][1] + b1 };
            float2 w1 = { acc[i][j][2] + b0, acc[i][j][3] + b1 };
            *(float2*)(out + (size_t)row * 128 + col)       = w0;
            *(float2*)(out + (size_t)(row + 8) * 128 + col) = w1;
        }
    }
}

extern "C" void kernel_launch(void* const* d_in, const int* in_sizes, int n_in,
                              void* d_out, int out_size)
{
    const float* x          = (const float*)d_in[0];
    const float* x_nei_rel  = (const float*)d_in[1];
    const float* x_nei_node = (const float*)d_in[2];
    const float* W1_w       = (const float*)d_in[3];
    const float* W1_b       = (const float*)d_in[4];
    float* out = (float*)d_out;

    cudaFuncSetAttribute(k1_y,    cudaFuncAttributeMaxDynamicSharedMemorySize, K1_BYTES);
    cudaFuncSetAttribute(k2_attn, cudaFuncAttributeMaxDynamicSharedMemorySize, K2_BYTES);
    cudaFuncSetAttribute(k3_out,  cudaFuncAttributeMaxDynamicSharedMemorySize, K3_BYTES);

    // K1: plain launch
    k1_y<<<256, 256, K1_BYTES>>>(x, W1_w);

    // K2/K3: programmatic dependent launches (overlap with predecessor's drain)
    cudaLaunchAttribute attr[1];
    attr[0].id = cudaLaunchAttributeProgrammaticStreamSerialization;
    attr[0].val.programmaticStreamSerializationAllowed = 1;

    {
        cudaLaunchConfig_t cfg = {};
        cfg.gridDim = dim3(8, 512);
        cfg.blockDim = dim3(256);
        cfg.dynamicSmemBytes = K2_BYTES;
        cfg.stream = 0;
        cfg.attrs = attr;
        cfg.numAttrs = 1;
        cudaLaunchKernelEx(&cfg, k2_attn, x_nei_rel, x_nei_node);
    }
    {
        cudaLaunchConfig_t cfg = {};
        cfg.gridDim = dim3(256);
        cfg.blockDim = dim3(256);
        cfg.dynamicSmemBytes = K3_BYTES;
        cfg.stream = 0;
        cfg.attrs = attr;
        cfg.numAttrs = 1;
        cudaLaunchKernelEx(&cfg, k3_out, W1_w, W1_b, out);
    }
}

// round 17
// speedup vs baseline: 1.1300x; 1.0100x over previous
#include <cuda_runtime.h>
#include <cuda_fp16.h>
#include <cstdint>

// NeiAttention, 3-kernel PDL form (round 17 = R16 with EARLY triggers).
// Trigger fires at kernel start -> secondary launches immediately; its pre-sync
// work (K2: A streaming, K3: W staging) overlaps the primary's full runtime.
// gridDepSync still guarantees y/z visibility.

__device__ __half g_y16[16384 * 192];
__device__ __half g_z16[16384 * 192];

__device__ __forceinline__ uint32_t smem_u32(const void* p) {
    uint32_t a;
    asm("{ .reg .u64 t; cvta.to.shared.u64 t, %1; cvt.u32.u64 %0, t; }" : "=r"(a) : "l"(p));
    return a;
}
__device__ __forceinline__ uint32_t pack_f16x2(float lo, float hi) {
    uint32_t r;
    asm("cvt.rn.f16x2.f32 %0, %1, %2;" : "=r"(r) : "f"(hi), "f"(lo));
    return r;
}
__device__ __forceinline__ void ldsm4(uint32_t r[4], uint32_t addr) {
    asm volatile("ldmatrix.sync.aligned.m8n8.x4.shared.b16 {%0,%1,%2,%3}, [%4];"
                 : "=r"(r[0]), "=r"(r[1]), "=r"(r[2]), "=r"(r[3]) : "r"(addr));
}
__device__ __forceinline__ void ldsm4t(uint32_t r[4], uint32_t addr) {
    asm volatile("ldmatrix.sync.aligned.m8n8.x4.trans.shared.b16 {%0,%1,%2,%3}, [%4];"
                 : "=r"(r[0]), "=r"(r[1]), "=r"(r[2]), "=r"(r[3]) : "r"(addr));
}
__device__ __forceinline__ void mma_f16(float d[4], const uint32_t a[4],
                                        uint32_t b0, uint32_t b1) {
    asm volatile(
        "mma.sync.aligned.m16n8k16.row.col.f32.f16.f16.f32 "
        "{%0,%1,%2,%3}, {%4,%5,%6,%7}, {%8,%9}, {%0,%1,%2,%3};"
        : "+f"(d[0]), "+f"(d[1]), "+f"(d[2]), "+f"(d[3])
        : "r"(a[0]), "r"(a[1]), "r"(a[2]), "r"(a[3]), "r"(b0), "r"(b1));
}
__device__ __forceinline__ void cpa16(uint32_t dst, const void* src) {
    asm volatile("cp.async.cg.shared.global [%0], [%1], 16;" :: "r"(dst), "l"(src));
}
__device__ __forceinline__ void cp_commit() { asm volatile("cp.async.commit_group;" ::: "memory"); }
template <int N>
__device__ __forceinline__ void cp_wait() { asm volatile("cp.async.wait_group %0;" :: "n"(N) : "memory"); }
__device__ __forceinline__ float shflx(float v, int m) { return __shfl_xor_sync(0xffffffffu, v, m); }

// ============================ K1: y = x @ W ============================
#define K1_XH   0         // 64*68  = 4352 w
#define K1_WH   4352      // 128*100 = 12800 w
#define K1_WORDS 17152
#define K1_BYTES (K1_WORDS * 4)   // 68,608 B

__global__ __launch_bounds__(256, 2)
void k1_y(const float* __restrict__ x, const float* __restrict__ W1_w)
{
    // EARLY trigger: let K2 launch now; K2's A-stream is independent of y.
    cudaTriggerProgrammaticLaunchCompletion();

    extern __shared__ float sm[];
    const uint32_t sb = smem_u32(sm);
    const int tid = threadIdx.x;
    const int wid = tid >> 5, lid = tid & 31;
    const int g = lid >> 2, t4 = lid & 3;
    const int sel = lid >> 3, lr = lid & 7;
    const int wm = wid >> 2, wn = wid & 3;

    // stage x tile (64 rows, fp16, stride 68 words)
    {
        const float4* xp = (const float4*)(x + (size_t)blockIdx.x * 64 * 128);
        #pragma unroll
        for (int it = 0; it < 8; it++) {
            int idx = tid + it * 256;
            int r = idx >> 5, c = idx & 31;
            float4 v = xp[idx];
            uint2 w;
            w.x = pack_f16x2(v.x, v.y);
            w.y = pack_f16x2(v.z, v.w);
            *(uint2*)((uint32_t*)sm + K1_XH + r * 68 + 2 * c) = w;
        }
    }
    // stage W natural [d][k'] fp16 (stride 100 words)
    {
        const float4* Wv = (const float4*)W1_w;
        #pragma unroll
        for (int it = 0; it < 24; it++) {
            int idx = tid + it * 256;
            int d = idx / 48, c = idx - d * 48;
            float4 v = Wv[idx];
            uint2 w;
            w.x = pack_f16x2(v.x, v.y);
            w.y = pack_f16x2(v.z, v.w);
            *(uint2*)((uint32_t*)sm + K1_WH + d * 100 + 2 * c) = w;
        }
    }
    __syncthreads();

    uint32_t aA[2];
    #pragma unroll
    for (int i = 0; i < 2; i++)
        aA[i] = sb + K1_XH * 4 + (uint32_t)(wm * 32 + i * 16 + (sel & 1) * 8 + lr) * 272u
                + (uint32_t)(sel >> 1) * 16u;
    const int drow = (lid & 7) + ((lid >> 3) & 1) * 8;
    const int kgrp = lid >> 4;
    uint32_t bT[3];
    #pragma unroll
    for (int jp = 0; jp < 3; jp++)
        bT[jp] = sb + K1_WH * 4 + (uint32_t)drow * 400u
                 + (uint32_t)(wn * 48 + jp * 16 + kgrp * 8) * 2u;

    float acc[2][6][4];
    #pragma unroll
    for (int i = 0; i < 2; i++)
        #pragma unroll
        for (int j = 0; j < 6; j++)
            #pragma unroll
            for (int q = 0; q < 4; q++) acc[i][j][q] = 0.f;

    #pragma unroll
    for (int ks = 0; ks < 8; ks++) {
        uint32_t a0[4], a1[4];
        ldsm4(a0, aA[0] + ks * 32);
        ldsm4(a1, aA[1] + ks * 32);
        #pragma unroll
        for (int jp = 0; jp < 3; jp++) {
            uint32_t bt[4];
            ldsm4t(bt, bT[jp] + ks * 6400);
            mma_f16(acc[0][2 * jp],     a0, bt[0], bt[1]);
            mma_f16(acc[0][2 * jp + 1], a0, bt[2], bt[3]);
            mma_f16(acc[1][2 * jp],     a1, bt[0], bt[1]);
            mma_f16(acc[1][2 * jp + 1], a1, bt[2], bt[3]);
        }
    }

    #pragma unroll
    for (int i = 0; i < 2; i++) {
        int row = blockIdx.x * 64 + wm * 32 + i * 16 + g;
        #pragma unroll
        for (int j = 0; j < 6; j++) {
            int col = wn * 48 + j * 8 + 2 * t4;
            *(uint32_t*)(g_y16 + (size_t)row * 192 + col) =
                pack_f16x2(acc[i][j][0], acc[i][j][1]);
            *(uint32_t*)(g_y16 + (size_t)(row + 8) * 192 + col) =
                pack_f16x2(acc[i][j][2], acc[i][j][3]);
        }
    }
}

// ============== K2: logits, softmax, z — 64-row tiles, 4 CTAs/SM, PDL ==============
#define K2_AST  196
#define K2_SA   0         // 64*196 = 12544 w
#define K2_SY   12544     // 384 w
#define K2_LOG  12928     // 64
#define K2_EX   12992     // 64
#define K2_AL   13056     // 64
#define K2_WORDS 13120
#define K2_BYTES (K2_WORDS * 4)   // 52,480 B

__global__ __launch_bounds__(256, 4)
void k2_attn(const float* __restrict__ x_nei_rel,
             const float* __restrict__ x_nei_node)
{
    // EARLY trigger: let K3 launch; its W staging is independent of z.
    cudaTriggerProgrammaticLaunchCompletion();

    extern __shared__ float sm[];
    const uint32_t sb = smem_u32(sm);
    float*  sA  = sm + K2_SA;
    __half* sYh = (__half*)(sm + K2_SY);
    float*  sLog= sm + K2_LOG;
    float*  sE  = sm + K2_EX;
    float*  sAl = sm + K2_AL;
    const uint32_t aU = sb + K2_SA * 4, yU = sb + K2_SY * 4;

    const int tid = threadIdx.x;
    const int b = blockIdx.y, nc = blockIdx.x;
    const size_t row0  = (size_t)b * 512 + (size_t)nc * 64;
    const int    nbase = b * 32 + nc * 4;

    // ---- A streaming: issued BEFORE gridDepSync (independent of K1) ----
    {
        const float4* rp = (const float4*)(x_nei_rel + row0 * 64);
        #pragma unroll
        for (int it = 0; it < 4; it++) {
            int idx = tid + it * 256;
            int r = idx >> 4, c = idx & 15;
            cpa16(aU + (uint32_t)(r * K2_AST + c * 4) * 4u, rp + r * 16 + c);
        }
        const float4* np = (const float4*)(x_nei_node + row0 * 128);
        #pragma unroll
        for (int it = 0; it < 2; it++) {
            int idx = tid + it * 256;
            int r = idx >> 3, c = idx & 7;
            cpa16(aU + (uint32_t)(r * K2_AST + 64 + c * 4) * 4u, np + r * 32 + c);
        }
        #pragma unroll
        for (int it = 0; it < 6; it++) {
            int idx = tid + it * 256;
            int r = idx / 24, c = idx - r * 24;
            cpa16(aU + (uint32_t)(r * K2_AST + 96 + c * 4) * 4u, np + r * 32 + 8 + c);
        }
        cp_commit();
    }

    // ---- wait for K1 completion (y visible), then pull y ----
    cudaGridDependencySynchronize();
    if (tid < 96)
        cpa16(yU + (uint32_t)tid * 16u, g_y16 + (size_t)nbase * 192 + tid * 8);
    cp_commit();

    cp_wait<0>();
    __syncthreads();

    // ---- dots: 4 threads per row, full K=192 ----
    const int r = tid >> 2, h = tid & 3;
    float s = 0.f;
    {
        const float*  ar = sA + r * K2_AST + h * 24;
        const __half* yr = sYh + (r >> 4) * 192 + h * 24;
        #pragma unroll
        for (int kk = 0; kk < 12; kk++) {
            float2 a2 = *(const float2*)(ar + 2 * kk);
            float2 yf = __half22float2(*(const __half2*)(yr + 2 * kk));
            s += a2.x * yf.x + a2.y * yf.y;
        }
    }
    {
        const float*  ar = sA + r * K2_AST + 96 + h * 24;
        const __half* yr = sYh + (r >> 4) * 192 + 96 + h * 24;
        #pragma unroll
        for (int kk = 0; kk < 12; kk++) {
            float2 a2 = *(const float2*)(ar + 2 * kk);
            float2 yf = __half22float2(*(const __half2*)(yr + 2 * kk));
            s += a2.x * yf.x + a2.y * yf.y;
        }
    }
    s += shflx(s, 1);
    s += shflx(s, 2);
    if (h == 0) sLog[r] = s * 0.08838834764831845f;   // 1/sqrt(128)
    __syncthreads();

    // ---- softmax over S=16 per node ----
    float e = 0.f;
    if (tid < 64) {
        int base = tid & ~15;
        float m = -1e30f;
        #pragma unroll
        for (int q = 0; q < 16; q++) m = fmaxf(m, sLog[base + q]);
        e = __expf(sLog[tid] - m);
        sE[tid] = e;
    }
    __syncthreads();
    if (tid < 64) {
        int base = tid & ~15;
        float den = 0.f;
        #pragma unroll
        for (int q = 0; q < 16; q++) den += sE[base + q];
        sAl[tid] = e / den;
    }
    __syncthreads();

    // ---- z = sum_s alpha * a -> fp16 ----
    #pragma unroll
    for (int p = 0; p < 2; p++) {
        int u = tid + 256 * p;
        if (u < 384) {
            int n = u / 96, dp = u - n * 96;
            const float* ap = sA + (n * 16) * K2_AST + 2 * dp;
            const float* al = sAl + n * 16;
            float z0 = 0.f, z1 = 0.f;
            #pragma unroll
            for (int q = 0; q < 16; q++) {
                float2 av = *(const float2*)(ap + q * K2_AST);
                float  a  = al[q];
                z0 += a * av.x;
                z1 += a * av.y;
            }
            *(uint32_t*)(g_z16 + (size_t)(nbase + n) * 192 + 2 * dp) = pack_f16x2(z0, z1);
        }
    }
}

// ============================ K3: out = z @ W^T + b, PDL ============================
#define K3_ZH   0         // 64*100 = 6400 w
#define K3_WH   6400      // 128*100 = 12800 w
#define K3_WORDS 19200
#define K3_BYTES (K3_WORDS * 4)   // 76,800 B

__global__ __launch_bounds__(256, 2)
void k3_out(const float* __restrict__ W1_w,
            const float* __restrict__ W1_b,
            float* __restrict__ out)
{
    extern __shared__ float sm[];
    const uint32_t sb = smem_u32(sm);
    const int tid = threadIdx.x;
    const int wid = tid >> 5, lid = tid & 31;
    const int g = lid >> 2, t4 = lid & 3;
    const int sel = lid >> 3, lr = lid & 7;
    const int wm = wid >> 2, wn = wid & 3;

    // ---- W staging (fp32 -> fp16): BEFORE gridDepSync, overlaps K2 tail ----
    {
        const float4* Wv = (const float4*)W1_w;
        #pragma unroll
        for (int it = 0; it < 24; it++) {
            int idx = tid + it * 256;
            int d = idx / 48, c = idx - d * 48;
            float4 v = Wv[idx];
            uint2 w;
            w.x = pack_f16x2(v.x, v.y);
            w.y = pack_f16x2(v.z, v.w);
            *(uint2*)((uint32_t*)sm + K3_WH + d * 100 + 2 * c) = w;
        }
    }

    // ---- wait for K2 completion (z visible), then pull z ----
    cudaGridDependencySynchronize();
    {
        const __half* zp = g_z16 + (size_t)blockIdx.x * 64 * 192;
        #pragma unroll
        for (int it = 0; it < 6; it++) {
            int idx = tid + it * 256;
            int r = idx / 24, c = idx - r * 24;
            cpa16(sb + K3_ZH * 4 + (uint32_t)(r * 100 + c * 4) * 4u, zp + r * 192 + c * 8);
        }
        cp_commit();
    }
    cp_wait<0>();
    __syncthreads();

    uint32_t aA[2], bA[2];
    #pragma unroll
    for (int i = 0; i < 2; i++)
        aA[i] = sb + K3_ZH * 4 + (uint32_t)(wm * 32 + i * 16 + (sel & 1) * 8 + lr) * 400u
                + (uint32_t)(sel >> 1) * 16u;
    #pragma unroll
    for (int jp = 0; jp < 2; jp++)
        bA[jp] = sb + K3_WH * 4 + (uint32_t)(wn * 32 + jp * 16 + (sel >> 1) * 8 + lr) * 400u
                 + (uint32_t)(sel & 1) * 16u;

    float acc[2][4][4];
    #pragma unroll
    for (int i = 0; i < 2; i++)
        #pragma unroll
        for (int j = 0; j < 4; j++)
            #pragma unroll
            for (int q = 0; q < 4; q++) acc[i][j][q] = 0.f;

    #pragma unroll
    for (int ks = 0; ks < 12; ks++) {
        uint32_t a0[4], a1[4], b0[4], b1[4];
        ldsm4(a0, aA[0] + ks * 32);
        ldsm4(a1, aA[1] + ks * 32);
        ldsm4(b0, bA[0] + ks * 32);
        ldsm4(b1, bA[1] + ks * 32);
        mma_f16(acc[0][0], a0, b0[0], b0[1]);
        mma_f16(acc[0][1], a0, b0[2], b0[3]);
        mma_f16(acc[0][2], a0, b1[0], b1[1]);
        mma_f16(acc[0][3], a0, b1[2], b1[3]);
        mma_f16(acc[1][0], a1, b0[0], b0[1]);
        mma_f16(acc[1][1], a1, b0[2], b0[3]);
        mma_f16(acc[1][2], a1, b1[0], b1[1]);
        mma_f16(acc[1][3], a1, b1[2], b1[3]);
    }

    #pragma unroll
    for (int i = 0; i < 2; i++) {
        int row = blockIdx.x * 64 + wm * 32 + i * 16 + g;
        #pragma unroll
        for (int j = 0; j < 4; j++) {
            int col = wn * 32 + j * 8 + 2 * t4;
            float b0 = __ldg(W1_b + col), b1 = __ldg(W1_b + col + 1);
            float2 w0 = { acc[i][j][0] + b0, acc[i][j][1] + b1 };
            float2 w1 = { acc[i][j][2] + b0, acc[i][j][3] + b1 };
            *(float2*)(out + (size_t)row * 128 + col)       = w0;
            *(float2*)(out + (size_t)(row + 8) * 128 + col) = w1;
        }
    }
}

extern "C" void kernel_launch(void* const* d_in, const int* in_sizes, int n_in,
                              void* d_out, int out_size)
{
    const float* x          = (const float*)d_in[0];
    const float* x_nei_rel  = (const float*)d_in[1];
    const float* x_nei_node = (const float*)d_in[2];
    const float* W1_w       = (const float*)d_in[3];
    const float* W1_b       = (const float*)d_in[4];
    float* out = (float*)d_out;

    cudaFuncSetAttribute(k1_y,    cudaFuncAttributeMaxDynamicSharedMemorySize, K1_BYTES);
    cudaFuncSetAttribute(k2_attn, cudaFuncAttributeMaxDynamicSharedMemorySize, K2_BYTES);
    cudaFuncSetAttribute(k3_out,  cudaFuncAttributeMaxDynamicSharedMemorySize, K3_BYTES);

    k1_y<<<256, 256, K1_BYTES>>>(x, W1_w);

    cudaLaunchAttribute attr[1];
    attr[0].id = cudaLaunchAttributeProgrammaticStreamSerialization;
    attr[0].val.programmaticStreamSerializationAllowed = 1;

    {
        cudaLaunchConfig_t cfg = {};
        cfg.gridDim = dim3(8, 512);
        cfg.blockDim = dim3(256);
        cfg.dynamicSmemBytes = K2_BYTES;
        cfg.stream = 0;
        cfg.attrs = attr;
        cfg.numAttrs = 1;
        cudaLaunchKernelEx(&cfg, k2_attn, x_nei_rel, x_nei_node);
    }
    {
        cudaLaunchConfig_t cfg = {};
        cfg.gridDim = dim3(256);
        cfg.blockDim = dim3(256);
        cfg.dynamicSmemBytes = K3_BYTES;
        cfg.stream = 0;
        cfg.attrs = attr;
        cfg.numAttrs = 1;
        cudaLaunchKernelEx(&cfg, k3_out, W1_w, W1_b, out);
    }
}